// round 5
// baseline (speedup 1.0000x reference)
#include <cuda_runtime.h>
#include <cuda_bf16.h>
#include <cstdint>

#define BB 4
#define HH 16
#define SSZ 2048
#define DH 64
#define TQ 64
#define TK 64
#define NTH 128
#define NT (SSZ / TK)
#define NELEM (BB * HH * SSZ * DH)

// bf16 tiles: 64 rows x (64 + 8 pad) elems -> 144-byte row stride
#define ROWB 144
#define OFF_KLO 9216
#define OFF_VHI 18432
#define OFF_VLO 27648
#define BUFSZ 36864
#define SM_BYTES (2 * BUFSZ)

// bf16 hi/lo scratch (Q pre-scaled by 0.125)
__device__ __nv_bfloat16 g_qh[NELEM], g_ql[NELEM];
__device__ __nv_bfloat16 g_kh[NELEM], g_kl[NELEM];
__device__ __nv_bfloat16 g_vh[NELEM], g_vl[NELEM];

// ---------------- PTX helpers (base compute_103 features only) ----------------
__device__ __forceinline__ uint32_t smem_u32(const void* p) {
    uint32_t a;
    asm("{ .reg .u64 t; cvta.to.shared.u64 t, %1; cvt.u32.u64 %0, t; }" : "=r"(a) : "l"(p));
    return a;
}
__device__ __forceinline__ void ldsm4(unsigned* r, uint32_t a) {
    asm volatile("ldmatrix.sync.aligned.m8n8.x4.shared.b16 {%0,%1,%2,%3}, [%4];"
        : "=r"(r[0]), "=r"(r[1]), "=r"(r[2]), "=r"(r[3]) : "r"(a));
}
__device__ __forceinline__ void ldsm4t(unsigned* r, uint32_t a) {
    asm volatile("ldmatrix.sync.aligned.m8n8.x4.trans.shared.b16 {%0,%1,%2,%3}, [%4];"
        : "=r"(r[0]), "=r"(r[1]), "=r"(r[2]), "=r"(r[3]) : "r"(a));
}
__device__ __forceinline__ void hmma(float* c, const unsigned* a, unsigned b0, unsigned b1) {
    asm volatile("mma.sync.aligned.m16n8k16.row.col.f32.bf16.bf16.f32 "
        "{%0,%1,%2,%3}, {%4,%5,%6,%7}, {%8,%9}, {%0,%1,%2,%3};"
        : "+f"(c[0]), "+f"(c[1]), "+f"(c[2]), "+f"(c[3])
        : "r"(a[0]), "r"(a[1]), "r"(a[2]), "r"(a[3]), "r"(b0), "r"(b1));
}
__device__ __forceinline__ void cpa16(uint32_t dst, const void* src) {
    asm volatile("cp.async.cg.shared.global [%0], [%1], 16;" :: "r"(dst), "l"(src));
}
#define CP_COMMIT() asm volatile("cp.async.commit_group;" ::: "memory")
#define CP_WAIT1()  asm volatile("cp.async.wait_group 1;"  ::: "memory")

__device__ __forceinline__ unsigned cvt2(float hi, float lo) {
    unsigned r; asm("cvt.rn.bf16x2.f32 %0, %1, %2;" : "=r"(r) : "f"(hi), "f"(lo));
    return r;
}
__device__ __forceinline__ void split2(float a, float b, unsigned& h, unsigned& l) {
    h = cvt2(b, a);
    float ra = a - __uint_as_float(h << 16);
    float rb = b - __uint_as_float(h & 0xFFFF0000u);
    l = cvt2(rb, ra);
}
__device__ __forceinline__ void split8(float4 x, float4 y, uint4& hi, uint4& lo) {
    split2(x.x, x.y, hi.x, lo.x);
    split2(x.z, x.w, hi.y, lo.y);
    split2(y.x, y.y, hi.z, lo.z);
    split2(y.z, y.w, hi.w, lo.w);
}

// FMA-only expf (avoids MUFU throughput limit: ~540M exps with recompute)
__device__ __forceinline__ float fexp(float x) {
    x = fmaxf(x, -80.0f);
    float t = fmaf(x, 1.4426950408889634f, 12582912.0f);
    int ni = __float_as_int(t) << 23;
    float n = t - 12582912.0f;
    float r = fmaf(n, -0.693359375f, x);
    r = fmaf(n, 2.12194440e-4f, r);
    float p = 1.3888889e-3f;
    p = fmaf(p, r, 8.3333333e-3f);
    p = fmaf(p, r, 4.1666668e-2f);
    p = fmaf(p, r, 1.6666667e-1f);
    p = fmaf(p, r, 0.5f);
    p = fmaf(p, r, 1.0f);
    p = fmaf(p, r, 1.0f);
    return __int_as_float(__float_as_int(p) + ni);
}

// ---------------- pre-pass: f32 -> bf16 hi/lo scratch ----------------
__global__ void conv_kernel(const float* __restrict__ Q, const float* __restrict__ K,
                            const float* __restrict__ V) {
    size_t i = ((size_t)blockIdx.x * 256 + threadIdx.x) * 8;
    const float* s;
    __nv_bfloat16 *dh, *dl;
    float scale = 1.0f;
    if (blockIdx.y == 0)      { s = Q; dh = g_qh; dl = g_ql; scale = 0.125f; }
    else if (blockIdx.y == 1) { s = K; dh = g_kh; dl = g_kl; }
    else                      { s = V; dh = g_vh; dl = g_vl; }
    float4 x = *(const float4*)(s + i);
    float4 y = *(const float4*)(s + i + 4);
    x.x *= scale; x.y *= scale; x.z *= scale; x.w *= scale;
    y.x *= scale; y.y *= scale; y.z *= scale; y.w *= scale;
    uint4 hi, lo;
    split8(x, y, hi, lo);
    *(uint4*)((char*)dh + i * 2) = hi;
    *(uint4*)((char*)dl + i * 2) = lo;
}

// ---------------- tile prefetch / GEMM pieces ----------------
__device__ __forceinline__ void prefetch_kv(uint32_t dst, size_t src, int tid) {
    #pragma unroll
    for (int it = 0; it < 4; it++) {
        int idx = tid + NTH * it;
        int row = idx >> 3, g = idx & 7;
        size_t off = src + (size_t)row * DH + 8 * g;
        uint32_t d = dst + row * ROWB + g * 16;
        cpa16(d,           g_kh + off);
        cpa16(d + OFF_KLO, g_kl + off);
        cpa16(d + OFF_VHI, g_vh + off);
        cpa16(d + OFF_VLO, g_vl + off);
    }
}
__device__ __forceinline__ void prefetch_k(uint32_t dst, size_t src, int tid) {
    #pragma unroll
    for (int it = 0; it < 4; it++) {
        int idx = tid + NTH * it;
        int row = idx >> 3, g = idx & 7;
        size_t off = src + (size_t)row * DH + 8 * g;
        uint32_t d = dst + row * ROWB + g * 16;
        cpa16(d,           g_kh + off);
        cpa16(d + OFF_KLO, g_kl + off);
    }
}

__device__ __forceinline__ void gemm1(float sc[8][4], uint32_t kb,
                                      const unsigned qh[4][4], const unsigned ql[4][4],
                                      int krow_l, int kcolb_l) {
    #pragma unroll
    for (int c = 0; c < 4; c++) {
        #pragma unroll
        for (int p = 0; p < 4; p++) {
            unsigned kh4[4], kl4[4];
            uint32_t a = kb + (16 * p + krow_l) * ROWB + c * 32 + kcolb_l;
            ldsm4(kh4, a);
            ldsm4(kl4, a + OFF_KLO);
            hmma(sc[2 * p],     qh[c], kh4[0], kh4[1]);
            hmma(sc[2 * p + 1], qh[c], kh4[2], kh4[3]);
            hmma(sc[2 * p],     qh[c], kl4[0], kl4[1]);
            hmma(sc[2 * p + 1], qh[c], kl4[2], kl4[3]);
            hmma(sc[2 * p],     ql[c], kh4[0], kh4[1]);
            hmma(sc[2 * p + 1], ql[c], kh4[2], kh4[3]);
        }
    }
}

__device__ __forceinline__ void gemm2(float oacc[8][4], uint32_t vb,
                                      const unsigned pah[4][4], const unsigned pal[4][4],
                                      int vrow_l, int vcolb_l) {
    #pragma unroll
    for (int c = 0; c < 4; c++) {
        #pragma unroll
        for (int p = 0; p < 4; p++) {
            unsigned vh4[4], vl4[4];
            uint32_t a = vb + (16 * c + vrow_l) * ROWB + p * 32 + vcolb_l;
            ldsm4t(vh4, a);
            ldsm4t(vl4, a + (OFF_VLO - OFF_VHI));
            hmma(oacc[2 * p],     pah[c], vh4[0], vh4[1]);
            hmma(oacc[2 * p + 1], pah[c], vh4[2], vh4[3]);
            hmma(oacc[2 * p],     pah[c], vl4[0], vl4[1]);
            hmma(oacc[2 * p + 1], pah[c], vl4[2], vl4[3]);
            hmma(oacc[2 * p],     pal[c], vh4[0], vh4[1]);
            hmma(oacc[2 * p + 1], pal[c], vh4[2], vh4[3]);
        }
    }
}

extern __shared__ char smem[];

__global__ void __launch_bounds__(NTH, 3)
attn2_kernel(const int* __restrict__ M, float* __restrict__ Og, float* __restrict__ Pg,
             int wout, int wp)
{
    const uint32_t sb = smem_u32(smem);
    const int tid = threadIdx.x;
    const int lane = tid & 31, w = tid >> 5;
    const int q0 = blockIdx.x * TQ;
    const int hh = blockIdx.y, b = blockIdx.z;
    const size_t bh = (size_t)b * HH + hh;

    const size_t kvoff = bh * SSZ * DH;
    const size_t qoff  = kvoff + (size_t)q0 * DH;
    const int* Mg0 = M + ((size_t)b * SSZ + (size_t)q0) * SSZ;

    // group 0: Q hi/lo staged into buf1 region
    #pragma unroll
    for (int it = 0; it < 4; it++) {
        int idx = tid + NTH * it;           // 512 chunks
        int row = idx >> 3, g = idx & 7;
        size_t off = qoff + (size_t)row * DH + 8 * g;
        uint32_t d = sb + BUFSZ + row * ROWB + g * 16;
        cpa16(d,           g_qh + off);
        cpa16(d + OFF_KLO, g_ql + off);
    }
    CP_COMMIT();
    // group 1: K/V tile 0 into buf0
    prefetch_kv(sb, kvoff, tid);
    CP_COMMIT();
    CP_WAIT1();                             // Q staged
    __syncthreads();

    // Q fragments, register resident
    unsigned qh[4][4], ql[4][4];
    {
        int row = 16 * w + (lane & 15);
        int colb = (lane >> 4) << 4;
        #pragma unroll
        for (int c = 0; c < 4; c++) {
            uint32_t a = sb + BUFSZ + row * ROWB + c * 32 + colb;
            ldsm4(qh[c], a);
            ldsm4(ql[c], a + OFF_KLO);
        }
    }
    __syncthreads();                        // Q consumed before buf1 reuse

    float oacc[8][4];
    #pragma unroll
    for (int j = 0; j < 8; j++)
        #pragma unroll
        for (int i = 0; i < 4; i++) oacc[j][i] = 0.0f;
    float rs0 = 0.0f, rs1 = 0.0f;

    const int r0 = 16 * w + (lane >> 2);
    const int cbase = 2 * (lane & 3);
    const int* mR0 = Mg0 + (size_t)r0 * SSZ;
    const int* mR1 = mR0 + (size_t)8 * SSZ;

    const int krow_l  = ((lane >> 4) << 3) + (lane & 7);
    const int kcolb_l = ((lane >> 3) & 1) << 4;
    const int vrow_l  = (((lane >> 3) & 1) << 3) + (lane & 7);
    const int vcolb_l = (lane >> 4) << 4;

    // ================= pass A: rowsums + O accumulation =================
    #pragma unroll 1
    for (int t = 0; t < NT; t++) {
        const uint32_t cur = sb + (t & 1) * BUFSZ;
        if (t + 1 < NT)
            prefetch_kv(sb + ((t + 1) & 1) * BUFSZ, kvoff + (size_t)(t + 1) * TK * DH, tid);
        CP_COMMIT();
        CP_WAIT1();
        __syncthreads();

        const int k0 = t * TK;
        int2 m0a[8], m1a[8];
        #pragma unroll
        for (int j = 0; j < 8; j++) {
            int col = k0 + 8 * j + cbase;
            m0a[j] = *(const int2*)(mR0 + col);
            m1a[j] = *(const int2*)(mR1 + col);
        }

        float sc[8][4];
        #pragma unroll
        for (int j = 0; j < 8; j++)
            #pragma unroll
            for (int i = 0; i < 4; i++) sc[j][i] = 0.0f;
        gemm1(sc, cur, qh, ql, krow_l, kcolb_l);

        #pragma unroll
        for (int j = 0; j < 8; j++) {
            float e0 = (m0a[j].x == 1) ? 0.0f : fexp(sc[j][0]);
            float e1 = (m0a[j].y == 1) ? 0.0f : fexp(sc[j][1]);
            float e2 = (m1a[j].x == 1) ? 0.0f : fexp(sc[j][2]);
            float e3 = (m1a[j].y == 1) ? 0.0f : fexp(sc[j][3]);
            rs0 += e0 + e1;
            rs1 += e2 + e3;
            sc[j][0] = e0; sc[j][1] = e1; sc[j][2] = e2; sc[j][3] = e3;
        }

        unsigned pah[4][4], pal[4][4];
        #pragma unroll
        for (int c = 0; c < 4; c++) {
            split2(sc[2 * c][0],     sc[2 * c][1],     pah[c][0], pal[c][0]);
            split2(sc[2 * c][2],     sc[2 * c][3],     pah[c][1], pal[c][1]);
            split2(sc[2 * c + 1][0], sc[2 * c + 1][1], pah[c][2], pal[c][2]);
            split2(sc[2 * c + 1][2], sc[2 * c + 1][3], pah[c][3], pal[c][3]);
        }
        gemm2(oacc, cur + OFF_VHI, pah, pal, vrow_l, vcolb_l);
        __syncthreads();
    }

    // rowsum reduction within quads
    rs0 += __shfl_xor_sync(0xFFFFFFFFu, rs0, 1);
    rs0 += __shfl_xor_sync(0xFFFFFFFFu, rs0, 2);
    rs1 += __shfl_xor_sync(0xFFFFFFFFu, rs1, 1);
    rs1 += __shfl_xor_sync(0xFFFFFFFFu, rs1, 2);
    const float inv0 = (rs0 > 0.0f) ? (1.0f / rs0) : 0.0f;
    const float inv1 = (rs1 > 0.0f) ? (1.0f / rs1) : 0.0f;

    if (wout) {
        float* oR0 = Og + (bh * SSZ + (size_t)(q0 + r0)) * DH;
        float* oR1 = oR0 + (size_t)8 * DH;
        #pragma unroll
        for (int j = 0; j < 8; j++) {
            *(float2*)(oR0 + 8 * j + cbase) = make_float2(oacc[j][0] * inv0, oacc[j][1] * inv0);
            *(float2*)(oR1 + 8 * j + cbase) = make_float2(oacc[j][2] * inv1, oacc[j][3] * inv1);
        }
    }

    // ================= pass B: recompute S, write normalized P =================
    if (wp) {
        float* pR0 = Pg + (bh * SSZ + (size_t)(q0 + r0)) * SSZ;
        float* pR1 = pR0 + (size_t)8 * SSZ;

        prefetch_k(sb, kvoff, tid);
        CP_COMMIT();

        #pragma unroll 1
        for (int t = 0; t < NT; t++) {
            const uint32_t cur = sb + (t & 1) * BUFSZ;
            if (t + 1 < NT)
                prefetch_k(sb + ((t + 1) & 1) * BUFSZ, kvoff + (size_t)(t + 1) * TK * DH, tid);
            CP_COMMIT();
            CP_WAIT1();
            __syncthreads();

            const int k0 = t * TK;
            int2 m0a[8], m1a[8];
            #pragma unroll
            for (int j = 0; j < 8; j++) {
                int col = k0 + 8 * j + cbase;
                m0a[j] = *(const int2*)(mR0 + col);
                m1a[j] = *(const int2*)(mR1 + col);
            }

            float sc[8][4];
            #pragma unroll
            for (int j = 0; j < 8; j++)
                #pragma unroll
                for (int i = 0; i < 4; i++) sc[j][i] = 0.0f;
            gemm1(sc, cur, qh, ql, krow_l, kcolb_l);

            #pragma unroll
            for (int j = 0; j < 8; j++) {
                int col = k0 + 8 * j + cbase;
                float e0 = (m0a[j].x == 1) ? 0.0f : fexp(sc[j][0]);
                float e1 = (m0a[j].y == 1) ? 0.0f : fexp(sc[j][1]);
                float e2 = (m1a[j].x == 1) ? 0.0f : fexp(sc[j][2]);
                float e3 = (m1a[j].y == 1) ? 0.0f : fexp(sc[j][3]);
                *(float2*)(pR0 + col) = make_float2(e0 * inv0, e1 * inv0);
                *(float2*)(pR1 + col) = make_float2(e2 * inv1, e3 * inv1);
            }
            __syncthreads();
        }
    }
}

extern "C" void kernel_launch(void* const* d_in, const int* in_sizes, int n_in,
                              void* d_out, int out_size) {
    const float* Q = (const float*)d_in[0];
    const float* K = (const float*)d_in[1];
    const float* V = (const float*)d_in[2];
    const int*   M = (const int*)d_in[3];

    const long long OUTE = (long long)BB * HH * SSZ * DH;
    const long long PE   = (long long)BB * HH * SSZ * SSZ;

    float* Og = nullptr; float* Pg = nullptr;
    int wout = 0, wp = 0;
    long long osz = (long long)out_size;
    if (osz >= OUTE + PE) { Og = (float*)d_out; Pg = Og + OUTE; wout = 1; wp = 1; }
    else if (osz == PE)   { Pg = (float*)d_out; wp = 1; }
    else                  { Og = (float*)d_out; wout = 1; }

    // Opt-in to >48KB dynamic smem (this was missing in R4 -> launch failure).
    static int smem_configured = 0;
    if (!smem_configured) {
        cudaFuncSetAttribute(attn2_kernel,
                             cudaFuncAttributeMaxDynamicSharedMemorySize, SM_BYTES);
        smem_configured = 1;
    }

    conv_kernel<<<dim3(NELEM / 8 / 256, 3), 256>>>(Q, K, V);

    dim3 grid(SSZ / TQ, HH, BB);
    attn2_kernel<<<grid, NTH, SM_BYTES>>>(M, Og, Pg, wout, wp);
}

// round 6
// speedup vs baseline: 1.2258x; 1.2258x over previous
#include <cuda_runtime.h>
#include <cuda_bf16.h>
#include <cstdint>

#define BB 4
#define HH 16
#define SSZ 2048
#define DH 64
#define TQ 64
#define TK 32
#define NTH 128
#define NT (SSZ / TK)
#define NELEM (BB * HH * SSZ * DH)

// bf16 tiles: rows x (64 + 8 pad) elems -> 144-byte row stride
#define ROWB 144
#define OFF_KLO 4608               /* 32*144 */
#define OFF_VHI 9216
#define OFF_VLO 13824
#define BUFSZ   18432
#define RED_OFF (2 * BUFSZ)
#define SM_BYTES (2 * BUFSZ + 256)
#define QLO_OFF 9216               /* Q staging: 64*144 hi, then lo */

// bf16 hi/lo scratch (Q pre-scaled by 0.125)
__device__ __nv_bfloat16 g_qh[NELEM], g_ql[NELEM];
__device__ __nv_bfloat16 g_kh[NELEM], g_kl[NELEM];
__device__ __nv_bfloat16 g_vh[NELEM], g_vl[NELEM];

// ---------------- PTX helpers (base compute_103 features only) ----------------
__device__ __forceinline__ uint32_t smem_u32(const void* p) {
    uint32_t a;
    asm("{ .reg .u64 t; cvta.to.shared.u64 t, %1; cvt.u32.u64 %0, t; }" : "=r"(a) : "l"(p));
    return a;
}
__device__ __forceinline__ void ldsm4(unsigned* r, uint32_t a) {
    asm volatile("ldmatrix.sync.aligned.m8n8.x4.shared.b16 {%0,%1,%2,%3}, [%4];"
        : "=r"(r[0]), "=r"(r[1]), "=r"(r[2]), "=r"(r[3]) : "r"(a));
}
__device__ __forceinline__ void ldsm4t(unsigned* r, uint32_t a) {
    asm volatile("ldmatrix.sync.aligned.m8n8.x4.trans.shared.b16 {%0,%1,%2,%3}, [%4];"
        : "=r"(r[0]), "=r"(r[1]), "=r"(r[2]), "=r"(r[3]) : "r"(a));
}
__device__ __forceinline__ void hmma(float* c, const unsigned* a, unsigned b0, unsigned b1) {
    asm volatile("mma.sync.aligned.m16n8k16.row.col.f32.bf16.bf16.f32 "
        "{%0,%1,%2,%3}, {%4,%5,%6,%7}, {%8,%9}, {%0,%1,%2,%3};"
        : "+f"(c[0]), "+f"(c[1]), "+f"(c[2]), "+f"(c[3])
        : "r"(a[0]), "r"(a[1]), "r"(a[2]), "r"(a[3]), "r"(b0), "r"(b1));
}
__device__ __forceinline__ void cpa16(uint32_t dst, const void* src) {
    asm volatile("cp.async.cg.shared.global [%0], [%1], 16;" :: "r"(dst), "l"(src));
}
#define CP_COMMIT() asm volatile("cp.async.commit_group;" ::: "memory")
#define CP_WAIT1()  asm volatile("cp.async.wait_group 1;"  ::: "memory")

__device__ __forceinline__ unsigned cvt2(float hi, float lo) {
    unsigned r; asm("cvt.rn.bf16x2.f32 %0, %1, %2;" : "=r"(r) : "f"(hi), "f"(lo));
    return r;
}
__device__ __forceinline__ void split2(float a, float b, unsigned& h, unsigned& l) {
    h = cvt2(b, a);
    float ra = a - __uint_as_float(h << 16);
    float rb = b - __uint_as_float(h & 0xFFFF0000u);
    l = cvt2(rb, ra);
}
__device__ __forceinline__ void split8(float4 x, float4 y, uint4& hi, uint4& lo) {
    split2(x.x, x.y, hi.x, lo.x);
    split2(x.z, x.w, hi.y, lo.y);
    split2(y.x, y.y, hi.z, lo.z);
    split2(y.z, y.w, hi.w, lo.w);
}

// FMA-only expf (avoids MUFU throughput limit on 268M exps)
__device__ __forceinline__ float fexp(float x) {
    x = fmaxf(x, -80.0f);
    float t = fmaf(x, 1.4426950408889634f, 12582912.0f);
    int ni = __float_as_int(t) << 23;
    float n = t - 12582912.0f;
    float r = fmaf(n, -0.693359375f, x);
    r = fmaf(n, 2.12194440e-4f, r);
    float p = 1.3888889e-3f;
    p = fmaf(p, r, 8.3333333e-3f);
    p = fmaf(p, r, 4.1666668e-2f);
    p = fmaf(p, r, 1.6666667e-1f);
    p = fmaf(p, r, 0.5f);
    p = fmaf(p, r, 1.0f);
    p = fmaf(p, r, 1.0f);
    return __int_as_float(__float_as_int(p) + ni);
}

// ---------------- pre-pass: f32 -> bf16 hi/lo scratch ----------------
__global__ void conv_kernel(const float* __restrict__ Q, const float* __restrict__ K,
                            const float* __restrict__ V) {
    size_t i = ((size_t)blockIdx.x * 256 + threadIdx.x) * 8;
    const float* s;
    __nv_bfloat16 *dh, *dl;
    float scale = 1.0f;
    if (blockIdx.y == 0)      { s = Q; dh = g_qh; dl = g_ql; scale = 0.125f; }
    else if (blockIdx.y == 1) { s = K; dh = g_kh; dl = g_kl; }
    else                      { s = V; dh = g_vh; dl = g_vl; }
    float4 x = *(const float4*)(s + i);
    float4 y = *(const float4*)(s + i + 4);
    x.x *= scale; x.y *= scale; x.z *= scale; x.w *= scale;
    y.x *= scale; y.y *= scale; y.z *= scale; y.w *= scale;
    uint4 hi, lo;
    split8(x, y, hi, lo);
    *(uint4*)((char*)dh + i * 2) = hi;
    *(uint4*)((char*)dl + i * 2) = lo;
}

// prefetch one 32-row K/V hi+lo tile (256 chunks per region, 2 iters x 128 thr)
__device__ __forceinline__ void prefetch_kv(uint32_t dst, size_t src, int tid) {
    #pragma unroll
    for (int it = 0; it < 2; it++) {
        int idx = tid + NTH * it;
        int row = idx >> 3, g = idx & 7;
        size_t off = src + (size_t)row * DH + 8 * g;
        uint32_t d = dst + row * ROWB + g * 16;
        cpa16(d,           g_kh + off);
        cpa16(d + OFF_KLO, g_kl + off);
        cpa16(d + OFF_VHI, g_vh + off);
        cpa16(d + OFF_VLO, g_vl + off);
    }
}

extern __shared__ char smem[];

__global__ void __launch_bounds__(NTH, 4)
attn3_kernel(const int* __restrict__ M, float* __restrict__ Og, float* __restrict__ Pg,
             int wout, int wp)
{
    const uint32_t sb = smem_u32(smem);
    const int tid = threadIdx.x;
    const int lane = tid & 31, w = tid >> 5;
    const int q0 = blockIdx.x * TQ;
    const int hh = blockIdx.y, b = blockIdx.z;
    const size_t bh = (size_t)b * HH + hh;

    const size_t kvoff = bh * SSZ * DH;
    const size_t qoff  = kvoff + (size_t)q0 * DH;
    const int* Mg0 = M + ((size_t)b * SSZ + (size_t)q0) * SSZ;

    // group 0: Q hi/lo -> buf1 (exactly fills 18432 B)
    #pragma unroll
    for (int it = 0; it < 4; it++) {
        int idx = tid + NTH * it;
        int row = idx >> 3, g = idx & 7;
        size_t off = qoff + (size_t)row * DH + 8 * g;
        uint32_t d = sb + BUFSZ + row * ROWB + g * 16;
        cpa16(d,           g_qh + off);
        cpa16(d + QLO_OFF, g_ql + off);
    }
    CP_COMMIT();
    prefetch_kv(sb, kvoff, tid);           // group 1: tile0 -> buf0
    CP_COMMIT();
    CP_WAIT1();                            // Q staged
    __syncthreads();

    // Q fragments, register resident for whole loop
    unsigned qh[4][4], ql[4][4];
    {
        int row = 16 * w + (lane & 15);
        int colb = (lane >> 4) << 4;
        #pragma unroll
        for (int c = 0; c < 4; c++) {
            uint32_t a = sb + BUFSZ + row * ROWB + c * 32 + colb;
            ldsm4(qh[c], a);
            ldsm4(ql[c], a + QLO_OFF);
        }
    }
    __syncthreads();                       // Q consumed before buf1 reuse
    prefetch_kv(sb + BUFSZ, kvoff + (size_t)TK * DH, tid);  // group 2: tile1 -> buf1
    CP_COMMIT();

    float oacc[8][4];
    #pragma unroll
    for (int j = 0; j < 8; j++)
        #pragma unroll
        for (int i = 0; i < 4; i++) oacc[j][i] = 0.0f;
    float rs0 = 0.0f, rs1 = 0.0f;

    const int r0 = 16 * w + (lane >> 2);
    const int cbase = 2 * (lane & 3);
    const int* mR0 = Mg0 + (size_t)r0 * SSZ;
    const int* mR1 = mR0 + (size_t)8 * SSZ;
    float* pR0 = Pg + (bh * SSZ + (size_t)(q0 + r0)) * SSZ;
    float* pR1 = pR0 + (size_t)8 * SSZ;

    const int krow_l  = ((lane >> 4) << 3) + (lane & 7);
    const int kcolb_l = ((lane >> 3) & 1) << 4;
    const int vrow_l  = (((lane >> 3) & 1) << 3) + (lane & 7);
    const int vcolb_l = (lane >> 4) << 4;

    #pragma unroll 1
    for (int t = 0; t < NT; t++) {
        CP_WAIT1();                        // tile t resident in buf[t&1]
        __syncthreads();
        const uint32_t cur = sb + (t & 1) * BUFSZ;
        const int k0 = t * TK;

        // mask regs first (hide global latency under GEMM1)
        int2 m0a[4], m1a[4];
        #pragma unroll
        for (int j = 0; j < 4; j++) {
            int col = k0 + 8 * j + cbase;
            m0a[j] = *(const int2*)(mR0 + col);
            m1a[j] = *(const int2*)(mR1 + col);
        }

        // ---- GEMM1: S(16x32 per warp) = Q K^T, 3-term split ----
        float sc[4][4];
        #pragma unroll
        for (int j = 0; j < 4; j++)
            #pragma unroll
            for (int i = 0; i < 4; i++) sc[j][i] = 0.0f;
        #pragma unroll
        for (int c = 0; c < 4; c++) {
            #pragma unroll
            for (int p = 0; p < 2; p++) {
                unsigned kh4[4], kl4[4];
                uint32_t a = cur + (16 * p + krow_l) * ROWB + c * 32 + kcolb_l;
                ldsm4(kh4, a);
                ldsm4(kl4, a + OFF_KLO);
                hmma(sc[2 * p],     qh[c], kh4[0], kh4[1]);
                hmma(sc[2 * p + 1], qh[c], kh4[2], kh4[3]);
                hmma(sc[2 * p],     qh[c], kl4[0], kl4[1]);
                hmma(sc[2 * p + 1], qh[c], kl4[2], kl4[3]);
                hmma(sc[2 * p],     ql[c], kh4[0], kh4[1]);
                hmma(sc[2 * p + 1], ql[c], kh4[2], kh4[3]);
            }
        }

        // ---- mask + exp + unnormalized P write + rowsum ----
        #pragma unroll
        for (int j = 0; j < 4; j++) {
            int col = k0 + 8 * j + cbase;
            float e0 = (m0a[j].x == 1) ? 0.0f : fexp(sc[j][0]);
            float e1 = (m0a[j].y == 1) ? 0.0f : fexp(sc[j][1]);
            float e2 = (m1a[j].x == 1) ? 0.0f : fexp(sc[j][2]);
            float e3 = (m1a[j].y == 1) ? 0.0f : fexp(sc[j][3]);
            rs0 += e0 + e1;
            rs1 += e2 + e3;
            if (wp) {
                *(float2*)(pR0 + col) = make_float2(e0, e1);
                *(float2*)(pR1 + col) = make_float2(e2, e3);
            }
            sc[j][0] = e0; sc[j][1] = e1; sc[j][2] = e2; sc[j][3] = e3;
        }

        // ---- relayout C-frags -> GEMM2 A-frags ----
        unsigned pah[2][4], pal[2][4];
        #pragma unroll
        for (int c = 0; c < 2; c++) {
            split2(sc[2 * c][0],     sc[2 * c][1],     pah[c][0], pal[c][0]);
            split2(sc[2 * c][2],     sc[2 * c][3],     pah[c][1], pal[c][1]);
            split2(sc[2 * c + 1][0], sc[2 * c + 1][1], pah[c][2], pal[c][2]);
            split2(sc[2 * c + 1][2], sc[2 * c + 1][3], pah[c][3], pal[c][3]);
        }

        // ---- GEMM2: O += P V ----
        #pragma unroll
        for (int c = 0; c < 2; c++) {
            #pragma unroll
            for (int p = 0; p < 4; p++) {
                unsigned vh4[4], vl4[4];
                uint32_t a = cur + OFF_VHI + (16 * c + vrow_l) * ROWB + p * 32 + vcolb_l;
                ldsm4t(vh4, a);
                ldsm4t(vl4, a + OFF_KLO);
                hmma(oacc[2 * p],     pah[c], vh4[0], vh4[1]);
                hmma(oacc[2 * p + 1], pah[c], vh4[2], vh4[3]);
                hmma(oacc[2 * p],     pah[c], vl4[0], vl4[1]);
                hmma(oacc[2 * p + 1], pah[c], vl4[2], vl4[3]);
                hmma(oacc[2 * p],     pal[c], vh4[0], vh4[1]);
                hmma(oacc[2 * p + 1], pal[c], vh4[2], vh4[3]);
            }
        }

        __syncthreads();                    // tile t consumed
        if (t + 2 < NT)
            prefetch_kv(cur, kvoff + (size_t)(t + 2) * TK * DH, tid);
        CP_COMMIT();
    }

    // rowsum reduction within quads
    rs0 += __shfl_xor_sync(0xFFFFFFFFu, rs0, 1);
    rs0 += __shfl_xor_sync(0xFFFFFFFFu, rs0, 2);
    rs1 += __shfl_xor_sync(0xFFFFFFFFu, rs1, 1);
    rs1 += __shfl_xor_sync(0xFFFFFFFFu, rs1, 2);
    const float inv0 = (rs0 > 0.0f) ? (1.0f / rs0) : 0.0f;
    const float inv1 = (rs1 > 0.0f) ? (1.0f / rs1) : 0.0f;

    if (wout) {
        float* oR0 = Og + (bh * SSZ + (size_t)(q0 + r0)) * DH;
        float* oR1 = oR0 + (size_t)8 * DH;
        #pragma unroll
        for (int j = 0; j < 8; j++) {
            *(float2*)(oR0 + 8 * j + cbase) = make_float2(oacc[j][0] * inv0, oacc[j][1] * inv0);
            *(float2*)(oR1 + 8 * j + cbase) = make_float2(oacc[j][2] * inv1, oacc[j][3] * inv1);
        }
    }

    // in-place normalize of this CTA's own P slice (mostly L2-resident RMW)
    if (wp) {
        float* sred = (float*)(smem + RED_OFF);
        if ((lane & 3) == 0) { sred[r0] = inv0; sred[r0 + 8] = inv1; }
        __syncthreads();
        float4* pr = (float4*)(Pg + (bh * SSZ + (size_t)q0) * SSZ);
        #pragma unroll 8
        for (int i = 0; i < (TQ * SSZ / 4) / NTH; i++) {
            int idx = tid + NTH * i;
            float iv = sred[idx >> 9];
            float4 v = pr[idx];
            v.x *= iv; v.y *= iv; v.z *= iv; v.w *= iv;
            pr[idx] = v;
        }
    }
}

extern "C" void kernel_launch(void* const* d_in, const int* in_sizes, int n_in,
                              void* d_out, int out_size) {
    const float* Q = (const float*)d_in[0];
    const float* K = (const float*)d_in[1];
    const float* V = (const float*)d_in[2];
    const int*   M = (const int*)d_in[3];

    const long long OUTE = (long long)BB * HH * SSZ * DH;
    const long long PE   = (long long)BB * HH * SSZ * SSZ;

    float* Og = nullptr; float* Pg = nullptr;
    int wout = 0, wp = 0;
    long long osz = (long long)out_size;
    if (osz >= OUTE + PE) { Og = (float*)d_out; Pg = Og + OUTE; wout = 1; wp = 1; }
    else if (osz == PE)   { Pg = (float*)d_out; wp = 1; }
    else                  { Og = (float*)d_out; wout = 1; }

    static int smem_configured = 0;
    if (!smem_configured) {
        cudaFuncSetAttribute(attn3_kernel,
                             cudaFuncAttributeMaxDynamicSharedMemorySize, SM_BYTES);
        smem_configured = 1;
    }

    conv_kernel<<<dim3(NELEM / 8 / 256, 3), 256>>>(Q, K, V);

    dim3 grid(SSZ / TQ, HH, BB);
    attn3_kernel<<<grid, NTH, SM_BYTES>>>(M, Og, Pg, wout, wp);
}